// round 13
// baseline (speedup 1.0000x reference)
#include <cuda_runtime.h>
#include <cuda_bf16.h>
#include <cuda_fp16.h>
#include <cstdint>

#define N_NODES 100000
#define N_EDGES 1600000
#define D 128
#define K2 256

#define SCAN_NBLK ((N_NODES + 4095) / 4096)   // 25

// ---------------- scratch (device globals; no allocation allowed) ----------
__device__ int   g_deg[N_NODES];
__device__ int   g_off[N_NODES + 1];
__device__ int   g_cursor[N_NODES];
__device__ int   g_srcs[N_EDGES];
__device__ int   g_blksum[32];
__device__ float g_ahn[(size_t)N_NODES * D];        // aggregated feats (fp32)
__device__ __half2 g_h16[(size_t)N_NODES * 64];     // h in fp16 (gather copy)
__device__ __nv_bfloat16 g_Whi[128 * 256];          // W bf16 hi
__device__ __nv_bfloat16 g_Wlo[128 * 256];          // W bf16 lo

// ---------------- init: zero degrees + convert W to bf16 hi/lo ---------------
__global__ void k_init(const float* __restrict__ W) {
    int i = blockIdx.x * blockDim.x + threadIdx.x;
    if (i < N_NODES) g_deg[i] = 0;
    if (i < 128 * 256) {
        float v = W[i];
        __nv_bfloat16 hi = __float2bfloat16(v);
        g_Whi[i] = hi;
        g_Wlo[i] = __float2bfloat16(v - __bfloat162float(hi));
    }
}

// ---- count degrees AND convert h -> fp16 (disjoint thread ranges) -----------
__global__ void k_count_convh(const int* __restrict__ dst,
                              const float* __restrict__ h) {
    int i = blockIdx.x * blockDim.x + threadIdx.x;   // 0 .. 6.4M-1
    if (i < N_EDGES) atomicAdd(&g_deg[dst[i]], 1);
    if (i < N_NODES * 64) {
        float2 v = ((const float2*)h)[i];
        g_h16[i] = __floats2half2_rn(v.x, v.y);
    }
}

// ---- scan pass 1: per-block exclusive scan + block sums ---------------------
__global__ void k_scan1() {
    __shared__ int wsum[32];
    const int b = blockIdx.x, t = threadIdx.x;
    const int lane = t & 31, wid = t >> 5;
    const int base = b * 4096 + t * 4;

    int v0 = 0, v1 = 0, v2 = 0, v3 = 0;
    if (base + 3 < N_NODES) {
        int4 vv = *(const int4*)&g_deg[base];
        v0 = vv.x; v1 = vv.y; v2 = vv.z; v3 = vv.w;
    } else {
        if (base + 0 < N_NODES) v0 = g_deg[base + 0];
        if (base + 1 < N_NODES) v1 = g_deg[base + 1];
        if (base + 2 < N_NODES) v2 = g_deg[base + 2];
        if (base + 3 < N_NODES) v3 = g_deg[base + 3];
    }
    int tsum = v0 + v1 + v2 + v3;

    int x = tsum;
#pragma unroll
    for (int o = 1; o < 32; o <<= 1) {
        int y = __shfl_up_sync(0xffffffffu, x, o);
        if (lane >= o) x += y;
    }
    if (lane == 31) wsum[wid] = x;
    __syncthreads();
    if (wid == 0) {
        int w = wsum[lane];
        int xx = w;
#pragma unroll
        for (int o = 1; o < 32; o <<= 1) {
            int y = __shfl_up_sync(0xffffffffu, xx, o);
            if (lane >= o) xx += y;
        }
        wsum[lane] = xx - w;
        if (lane == 31) g_blksum[b] = xx;
    }
    __syncthreads();

    int prefix = wsum[wid] + (x - tsum);
    if (base + 3 < N_NODES) {
        *(int4*)&g_off[base] = make_int4(prefix, prefix + v0,
                                         prefix + v0 + v1, prefix + v0 + v1 + v2);
    } else {
        if (base + 0 < N_NODES) g_off[base + 0] = prefix;
        if (base + 1 < N_NODES) g_off[base + 1] = prefix + v0;
        if (base + 2 < N_NODES) g_off[base + 2] = prefix + v0 + v1;
        if (base + 3 < N_NODES) g_off[base + 3] = prefix + v0 + v1 + v2;
    }
}

// ---- scan pass 2: every block redundantly scans block sums, applies ---------
__global__ void k_scan23() {
    __shared__ int s_off;
    const int b = blockIdx.x, t = threadIdx.x;

    if (t < 32) {
        int v = (t < SCAN_NBLK) ? g_blksum[t] : 0;
        int x = v;
#pragma unroll
        for (int o = 1; o < 32; o <<= 1) {
            int y = __shfl_up_sync(0xffffffffu, x, o);
            if (t >= o) x += y;
        }
        if (t == b) s_off = x - v;
    }
    __syncthreads();
    const int off = s_off;

    const int base = b * 4096 + t * 4;
    if (base + 3 < N_NODES) {
        int4 vv = *(const int4*)&g_off[base];
        vv.x += off; vv.y += off; vv.z += off; vv.w += off;
        *(int4*)&g_off[base] = vv;
        *(int4*)&g_cursor[base] = vv;
    } else {
#pragma unroll
        for (int j = 0; j < 4; j++) {
            int idx = base + j;
            if (idx < N_NODES) {
                int val = g_off[idx] + off;
                g_off[idx] = val;
                g_cursor[idx] = val;
            }
        }
    }
    if (b == 0 && t == 0) g_off[N_NODES] = N_EDGES;
}

__global__ void k_scatter(const int* __restrict__ src, const int* __restrict__ dst) {
    int e = blockIdx.x * blockDim.x + threadIdx.x;
    if (e < N_EDGES) {
        int p = atomicAdd(&g_cursor[dst[e]], 1);
        g_srcs[p] = src[e];
    }
}

// ---------------- aggregation: fp16 gather, fp32 accumulate ------------------
// One warp per dst node; lane owns 4 cols (one uint2 = 4 halfs per row).
__global__ void k_aggregate() {
    int warp = (blockIdx.x * blockDim.x + threadIdx.x) >> 5;
    int lane = threadIdx.x & 31;
    if (warp >= N_NODES) return;
    int beg = g_off[warp];
    int end = g_off[warp + 1];
    const uint2* h2 = (const uint2*)g_h16;   // one uint2 = 4 halfs; row = 32
    float4 acc0 = make_float4(0.f, 0.f, 0.f, 0.f);
    float4 acc1 = make_float4(0.f, 0.f, 0.f, 0.f);
    int e = beg;
    for (; e + 3 < end; e += 4) {
        int s0 = __ldg(&g_srcs[e]);
        int s1 = __ldg(&g_srcs[e + 1]);
        int s2 = __ldg(&g_srcs[e + 2]);
        int s3 = __ldg(&g_srcs[e + 3]);
        uint2 u0 = __ldg(&h2[(size_t)s0 * 32 + lane]);
        uint2 u1 = __ldg(&h2[(size_t)s1 * 32 + lane]);
        uint2 u2 = __ldg(&h2[(size_t)s2 * 32 + lane]);
        uint2 u3 = __ldg(&h2[(size_t)s3 * 32 + lane]);
        float2 a0 = __half22float2(*(__half2*)&u0.x);
        float2 b0 = __half22float2(*(__half2*)&u0.y);
        float2 a1 = __half22float2(*(__half2*)&u1.x);
        float2 b1 = __half22float2(*(__half2*)&u1.y);
        float2 a2 = __half22float2(*(__half2*)&u2.x);
        float2 b2 = __half22float2(*(__half2*)&u2.y);
        float2 a3 = __half22float2(*(__half2*)&u3.x);
        float2 b3 = __half22float2(*(__half2*)&u3.y);
        acc0.x += a0.x; acc0.y += a0.y; acc0.z += b0.x; acc0.w += b0.y;
        acc1.x += a1.x; acc1.y += a1.y; acc1.z += b1.x; acc1.w += b1.y;
        acc0.x += a2.x; acc0.y += a2.y; acc0.z += b2.x; acc0.w += b2.y;
        acc1.x += a3.x; acc1.y += a3.y; acc1.z += b3.x; acc1.w += b3.y;
    }
    for (; e < end; e++) {
        int s0 = __ldg(&g_srcs[e]);
        uint2 u0 = __ldg(&h2[(size_t)s0 * 32 + lane]);
        float2 a0 = __half22float2(*(__half2*)&u0.x);
        float2 b0 = __half22float2(*(__half2*)&u0.y);
        acc0.x += a0.x; acc0.y += a0.y; acc0.z += b0.x; acc0.w += b0.y;
    }
    acc0.x += acc1.x; acc0.y += acc1.y; acc0.z += acc1.z; acc0.w += acc1.w;
    float norm = (end > beg) ? 1.0f / (float)(end - beg) : 0.0f;
    acc0.x *= norm; acc0.y *= norm; acc0.z *= norm; acc0.w *= norm;
    ((float4*)g_ahn)[(size_t)warp * 32 + lane] = acc0;
}

// =============== tensor-core GEMM + LN + ReLU (mma.sync bf16 hi/lo) ==========
#define ASTR 72
#define ABYTES (128 * ASTR * 2)
#define BUFBYTES (4 * ABYTES)
#define OFF_WHI 0
#define OFF_WLO (ABYTES)
#define OFF_AHI (2 * ABYTES)
#define OFF_ALO (3 * ABYTES)
#define TC_SMEM (2 * BUFBYTES)
#define OSTR 132

__device__ __forceinline__ uint32_t smem_u32(const void* p) {
    uint32_t a;
    asm("{ .reg .u64 t; cvta.to.shared.u64 t, %1; cvt.u32.u64 %0, t; }"
        : "=r"(a) : "l"(p));
    return a;
}

__device__ __forceinline__ void ldm4(uint32_t* r, uint32_t addr) {
    asm volatile("ldmatrix.sync.aligned.m8n8.x4.shared.b16 {%0,%1,%2,%3}, [%4];"
        : "=r"(r[0]), "=r"(r[1]), "=r"(r[2]), "=r"(r[3]) : "r"(addr));
}

__device__ __forceinline__ void mma_bf16(float* c, const uint32_t* a,
                                         uint32_t b0, uint32_t b1) {
    asm volatile("mma.sync.aligned.m16n8k16.row.col.f32.bf16.bf16.f32 "
        "{%0,%1,%2,%3}, {%4,%5,%6,%7}, {%8,%9}, {%0,%1,%2,%3};"
        : "+f"(c[0]), "+f"(c[1]), "+f"(c[2]), "+f"(c[3])
        : "r"(a[0]), "r"(a[1]), "r"(a[2]), "r"(a[3]), "r"(b0), "r"(b1));
}

__device__ __forceinline__ void split4(float4 v, uint32_t* hi, uint32_t* lo) {
    __nv_bfloat162 ha = __floats2bfloat162_rn(v.x, v.y);
    __nv_bfloat162 hb = __floats2bfloat162_rn(v.z, v.w);
    float2 fa = __bfloat1622float2(ha);
    float2 fb = __bfloat1622float2(hb);
    __nv_bfloat162 la = __floats2bfloat162_rn(v.x - fa.x, v.y - fa.y);
    __nv_bfloat162 lb = __floats2bfloat162_rn(v.z - fb.x, v.w - fb.y);
    hi[0] = *(uint32_t*)&ha; hi[1] = *(uint32_t*)&hb;
    lo[0] = *(uint32_t*)&la; lo[1] = *(uint32_t*)&lb;
}

__global__ void __launch_bounds__(512, 1)
k_gemm_tc(const float* __restrict__ h,
          const float* __restrict__ bias,
          const float* __restrict__ gamma,
          const float* __restrict__ beta,
          float* __restrict__ out)
{
    extern __shared__ char sm[];
    const uint32_t smb = smem_u32(sm);

    const int tid = threadIdx.x;
    const int wid = tid >> 5;
    const int lane = tid & 31;
    const int wm = wid & 3;
    const int wn = wid >> 2;
    const int row0 = blockIdx.x * 128;

    const int sr = tid >> 2;
    const int sq = tid & 3;

    const float4* h4 = (const float4*)h;
    const float4* a4 = (const float4*)g_ahn;

    float c[2][4][4];
#pragma unroll
    for (int i = 0; i < 2; i++)
#pragma unroll
        for (int j = 0; j < 4; j++)
#pragma unroll
            for (int k = 0; k < 4; k++) c[i][j][k] = 0.f;

    const int lrow = lane & 15;
    const int lhalfB = (lane >> 4) * 16;
    const uint32_t aRowB = (uint32_t)(wm * 32 + lrow) * (ASTR * 2);
    const uint32_t wRowB = (uint32_t)(wn * 32 + lrow) * (ASTR * 2);

    int growA = row0 + sr;
    if (growA >= N_NODES) growA = N_NODES - 1;
    const size_t aBase = (size_t)growA * 32;
    const int wIdx = sr * 256 + sq * 16;
    const uint32_t stByteOff = (uint32_t)((sr * ASTR + sq * 16) * 2);

    // ---- stage chunk 0 into buffer 0 ----------------------------------------
    {
        uint32_t hi[8], lo[8];
#pragma unroll
        for (int i = 0; i < 4; i++) {
            float4 v = __ldg(&h4[aBase + sq * 4 + i]);
            split4(v, &hi[2 * i], &lo[2 * i]);
        }
        char* pa = sm + OFF_AHI + stByteOff;
        char* pl = sm + OFF_ALO + stByteOff;
        *(uint4*)pa = make_uint4(hi[0], hi[1], hi[2], hi[3]);
        *(uint4*)(pa + 16) = make_uint4(hi[4], hi[5], hi[6], hi[7]);
        *(uint4*)pl = make_uint4(lo[0], lo[1], lo[2], lo[3]);
        *(uint4*)(pl + 16) = make_uint4(lo[4], lo[5], lo[6], lo[7]);

        uint4 wh0 = __ldg((const uint4*)&g_Whi[wIdx]);
        uint4 wh1 = __ldg((const uint4*)&g_Whi[wIdx + 8]);
        uint4 wl0 = __ldg((const uint4*)&g_Wlo[wIdx]);
        uint4 wl1 = __ldg((const uint4*)&g_Wlo[wIdx + 8]);
        char* pw = sm + OFF_WHI + stByteOff;
        char* pv = sm + OFF_WLO + stByteOff;
        *(uint4*)pw = wh0; *(uint4*)(pw + 16) = wh1;
        *(uint4*)pv = wl0; *(uint4*)(pv + 16) = wl1;
    }
    __syncthreads();

#pragma unroll
    for (int kb = 0; kb < 4; kb++) {
        const bool more = kb < 3;
        float4 preA[4];
        uint4 preW[4];
        if (more) {
            int kn = kb + 1;
            const float4* asrc = (kn < 2) ? h4 : a4;
            int koff = (kn & 1) * 16;
#pragma unroll
            for (int i = 0; i < 4; i++)
                preA[i] = __ldg(&asrc[aBase + koff + sq * 4 + i]);
            preW[0] = __ldg((const uint4*)&g_Whi[wIdx + kn * 64]);
            preW[1] = __ldg((const uint4*)&g_Whi[wIdx + kn * 64 + 8]);
            preW[2] = __ldg((const uint4*)&g_Wlo[wIdx + kn * 64]);
            preW[3] = __ldg((const uint4*)&g_Wlo[wIdx + kn * 64 + 8]);
        }

        const uint32_t bufB = (uint32_t)((kb & 1) * BUFBYTES);
#pragma unroll
        for (int ks = 0; ks < 4; ks++) {
            const uint32_t cb = (uint32_t)(ks * 32 + lhalfB);
            uint32_t ah[2][4], al[2][4], wh[2][4], wl[2][4];
#pragma unroll
            for (int mf = 0; mf < 2; mf++) {
                uint32_t ro = aRowB + mf * 16 * (ASTR * 2) + cb;
                ldm4(ah[mf], smb + bufB + OFF_AHI + ro);
                ldm4(al[mf], smb + bufB + OFF_ALO + ro);
            }
#pragma unroll
            for (int nx = 0; nx < 2; nx++) {
                uint32_t ro = wRowB + nx * 16 * (ASTR * 2) + cb;
                ldm4(wh[nx], smb + bufB + OFF_WHI + ro);
                ldm4(wl[nx], smb + bufB + OFF_WLO + ro);
            }
#pragma unroll
            for (int mf = 0; mf < 2; mf++)
#pragma unroll
                for (int nx = 0; nx < 2; nx++)
#pragma unroll
                    for (int sub = 0; sub < 2; sub++) {
                        int n8 = nx * 2 + sub;
                        mma_bf16(c[mf][n8], ah[mf], wh[nx][sub], wh[nx][sub + 2]);
                        mma_bf16(c[mf][n8], ah[mf], wl[nx][sub], wl[nx][sub + 2]);
                        mma_bf16(c[mf][n8], al[mf], wh[nx][sub], wh[nx][sub + 2]);
                    }
        }

        if (more) {
            const uint32_t nbB = (uint32_t)(((kb + 1) & 1) * BUFBYTES);
            uint32_t hi[8], lo[8];
#pragma unroll
            for (int i = 0; i < 4; i++)
                split4(preA[i], &hi[2 * i], &lo[2 * i]);
            char* pa = sm + nbB + OFF_AHI + stByteOff;
            char* pl = sm + nbB + OFF_ALO + stByteOff;
            *(uint4*)pa = make_uint4(hi[0], hi[1], hi[2], hi[3]);
            *(uint4*)(pa + 16) = make_uint4(hi[4], hi[5], hi[6], hi[7]);
            *(uint4*)pl = make_uint4(lo[0], lo[1], lo[2], lo[3]);
            *(uint4*)(pl + 16) = make_uint4(lo[4], lo[5], lo[6], lo[7]);
            char* pw = sm + nbB + OFF_WHI + stByteOff;
            char* pv = sm + nbB + OFF_WLO + stByteOff;
            *(uint4*)pw = preW[0]; *(uint4*)(pw + 16) = preW[1];
            *(uint4*)pv = preW[2]; *(uint4*)(pv + 16) = preW[3];
            __syncthreads();
        }
    }

    // ---- stage C frags to SMEM ------------------------------------------------
    __syncthreads();
    float* outS = (float*)sm;
#pragma unroll
    for (int mf = 0; mf < 2; mf++)
#pragma unroll
        for (int n8 = 0; n8 < 4; n8++) {
            int rr = wm * 32 + mf * 16 + (lane >> 2);
            int cc = wn * 32 + n8 * 8 + (lane & 3) * 2;
            *(float2*)&outS[rr * OSTR + cc] =
                make_float2(c[mf][n8][0], c[mf][n8][1]);
            *(float2*)&outS[(rr + 8) * OSTR + cc] =
                make_float2(c[mf][n8][2], c[mf][n8][3]);
        }
    __syncthreads();

    // ---- bias + LayerNorm + ReLU; 4 threads per row ----------------------------
    {
        int r = tid >> 2;
        int q = tid & 3;
        float vals[32];
        float s = 0.f, ss = 0.f;
#pragma unroll
        for (int j = 0; j < 8; j++) {
            int col = q * 32 + j * 4;
            float4 y = *(const float4*)&outS[r * OSTR + col];
            float4 bb = __ldg((const float4*)&bias[col]);
            y.x += bb.x; y.y += bb.y; y.z += bb.z; y.w += bb.w;
            vals[4 * j + 0] = y.x; vals[4 * j + 1] = y.y;
            vals[4 * j + 2] = y.z; vals[4 * j + 3] = y.w;
            s += y.x + y.y + y.z + y.w;
            ss += y.x * y.x + y.y * y.y + y.z * y.z + y.w * y.w;
        }
        s  += __shfl_xor_sync(0xffffffffu, s, 1);
        s  += __shfl_xor_sync(0xffffffffu, s, 2);
        ss += __shfl_xor_sync(0xffffffffu, ss, 1);
        ss += __shfl_xor_sync(0xffffffffu, ss, 2);
        float mu = s * (1.0f / 128.0f);
        float var = ss * (1.0f / 128.0f) - mu * mu;
        float inv = rsqrtf(var + 1e-5f);

        int grow = row0 + r;
        if (grow < N_NODES) {
            float* gout = &out[(size_t)grow * 128];
#pragma unroll
            for (int j = 0; j < 8; j++) {
                int col = q * 32 + j * 4;
                float4 gm = __ldg((const float4*)&gamma[col]);
                float4 bt = __ldg((const float4*)&beta[col]);
                float4 o;
                o.x = (vals[4 * j + 0] - mu) * inv * gm.x + bt.x;
                o.y = (vals[4 * j + 1] - mu) * inv * gm.y + bt.y;
                o.z = (vals[4 * j + 2] - mu) * inv * gm.z + bt.z;
                o.w = (vals[4 * j + 3] - mu) * inv * gm.w + bt.w;
                o.x = o.x > 0.f ? o.x : 0.f;
                o.y = o.y > 0.f ? o.y : 0.f;
                o.z = o.z > 0.f ? o.z : 0.f;
                o.w = o.w > 0.f ? o.w : 0.f;
                *(float4*)&gout[col] = o;
            }
        }
    }
}

// ---------------- launcher ---------------------------------------------------
extern "C" void kernel_launch(void* const* d_in, const int* in_sizes, int n_in,
                              void* d_out, int out_size) {
    const float* h     = (const float*)d_in[0];
    const float* W     = (const float*)d_in[1];
    const float* b     = (const float*)d_in[2];
    const float* gamma = (const float*)d_in[3];
    const float* beta  = (const float*)d_in[4];
    const int*   src   = (const int*)d_in[5];
    const int*   dst   = (const int*)d_in[6];
    float* out = (float*)d_out;

    static int inited = 0;
    if (!inited) {
        cudaFuncSetAttribute(k_gemm_tc, cudaFuncAttributeMaxDynamicSharedMemorySize,
                             TC_SMEM);
        inited = 1;
    }

    k_init<<<(N_NODES + 255) / 256, 256>>>(W);
    k_count_convh<<<(N_NODES * 64 + 255) / 256, 256>>>(dst, h);
    k_scan1<<<SCAN_NBLK, 1024>>>();
    k_scan23<<<SCAN_NBLK, 1024>>>();
    k_scatter<<<(N_EDGES + 255) / 256, 256>>>(src, dst);
    k_aggregate<<<(N_NODES * 32 + 255) / 256, 256>>>();
    const int GBLK = (N_NODES + 127) / 128;   // 782
    k_gemm_tc<<<GBLK, 512, TC_SMEM>>>(h, b, gamma, beta, out);
}